// round 1
// baseline (speedup 1.0000x reference)
#include <cuda_runtime.h>
#include <cstdint>

// Problem constants
#define Bb 8
#define Cc 512
#define Tt 4096
#define Gg 2
#define NCc 1024
#define Ee 256
#define Nrows (Bb * Tt)          // 32768 rows per group
#define QELEMS (Bb * Cc * Tt)    // 16777216
#define BM 64
#define BN 128
#define BK 32
#define NTHREADS 256
#define ROWTILES (Nrows / BM)    // 512

// Scratch (static device globals — no allocation)
__device__ float  g_resid[QELEMS];                 // residual after step 1 (B,C,T layout)
__device__ float  g_cnorm[2 * Gg * NCc];           // [codebook][g*NC + c]
__device__ double g_partial[2 * Gg * ROWTILES];    // [step][g*ROWTILES + tile]

// ---------------------------------------------------------------------------
// cnorm: sum of squares per codeword, both codebooks. One warp per codeword.
// ---------------------------------------------------------------------------
__global__ void cnorm_kernel(const float* __restrict__ cb1,
                             const float* __restrict__ cb2) {
    int gwarp = (blockIdx.x * blockDim.x + threadIdx.x) >> 5;
    int lane  = threadIdx.x & 31;
    if (gwarp >= 2 * Gg * NCc) return;
    const float* cb = (gwarp < Gg * NCc) ? cb1 : cb2;
    int row = gwarp & (Gg * NCc - 1);
    const float* p = cb + (size_t)row * Ee;
    float s = 0.f;
#pragma unroll
    for (int i = 0; i < Ee / 32; i++) {
        float v = p[lane + i * 32];
        s = __fadd_rn(s, __fmul_rn(v, v));   // square-then-add like jnp.sum(cb**2)
    }
#pragma unroll
    for (int off = 16; off; off >>= 1) s += __shfl_xor_sync(0xffffffffu, s, off);
    if (lane == 0) g_cnorm[gwarp] = s;
}

// ---------------------------------------------------------------------------
// One VQ step. Grid: (ROWTILES, G). Block: 256 threads (16x16), 64 rows,
// loops over 8 code tiles of 128 with K=256.
// ---------------------------------------------------------------------------
__global__ __launch_bounds__(NTHREADS, 2)
void vq_step_kernel(const float* __restrict__ xin,
                    const float* __restrict__ cb,
                    float* __restrict__ qout,
                    float* __restrict__ idxout,
                    int step) {
    extern __shared__ float sm[];
    float* xsAll  = sm;                          // [E][BM] 16384 f
    float* cs     = xsAll + Ee * BM;             // [BK][BN] 4096 f
    float* cnormS = cs + BK * BN;                // [BN]
    float* sxnorm = cnormS + BN;                 // [BM]
    unsigned long long* sbest =
        (unsigned long long*)(sxnorm + BM);      // [BM]  (8B aligned: offset 82688)

    const float* src = step ? g_resid : xin;
    const float* cnorm = g_cnorm + step * (Gg * NCc);
    double* partial = g_partial + step * (Gg * ROWTILES);

    int tid = threadIdx.x;
    int tx = tid & 15;    // code dim
    int ty = tid >> 4;    // row dim
    int g  = blockIdx.y;
    int n0 = blockIdx.x * BM;
    int b  = n0 >> 12;
    int t0 = n0 & (Tt - 1);
    size_t xbase = ((size_t)b * Cc + (size_t)g * Ee) * Tt + t0;

    // ---- Stage full x tile [E=256][BM=64] into smem (coalesced float4) ----
#pragma unroll
    for (int i = 0; i < (Ee * BM / 4) / NTHREADS; i++) {   // 16
        int f4 = tid + i * NTHREADS;
        int e  = f4 >> 4;
        int m4 = (f4 & 15) << 2;
        float4 v = *(const float4*)(src + xbase + (size_t)e * Tt + m4);
        *(float4*)&xsAll[e * BM + m4] = v;
    }
    __syncthreads();

    // ---- xnorm per row (square-then-add, order-insensitive by ulp argument)
    if (tid < BM) {
        float s = 0.f;
        for (int e = 0; e < Ee; e++) {
            float v = xsAll[e * BM + tid];
            s = __fadd_rn(s, __fmul_rn(v, v));
        }
        sxnorm[tid] = s;
        sbest[tid]  = ~0ull;
    }
    // (first sync inside the kt loop orders these before use)

    // ---- Loop over code tiles ----
    for (int ct = 0; ct < NCc / BN; ct++) {
        int c0 = ct * BN;
        if (tid < BN) cnormS[tid] = cnorm[g * NCc + c0 + tid];

        float acc[4][8];
#pragma unroll
        for (int i = 0; i < 4; i++)
#pragma unroll
            for (int j = 0; j < 8; j++) acc[i][j] = 0.f;

        for (int kt = 0; kt < Ee / BK; kt++) {
            __syncthreads();   // protect cs (and cnormS on first iter)
            // load cb tile [BN codes][BK e], store transposed cs[k][c]
#pragma unroll
            for (int i = 0; i < (BN * BK / 4) / NTHREADS; i++) {  // 4
                int f4 = tid + i * NTHREADS;
                int cr = f4 >> 3;
                int e4 = (f4 & 7) << 2;
                float4 v = *(const float4*)(cb +
                    ((size_t)(g * NCc + c0 + cr)) * Ee + kt * BK + e4);
                cs[(e4 + 0) * BN + cr] = v.x;
                cs[(e4 + 1) * BN + cr] = v.y;
                cs[(e4 + 2) * BN + cr] = v.z;
                cs[(e4 + 3) * BN + cr] = v.w;
            }
            __syncthreads();

#pragma unroll
            for (int k = 0; k < BK; k++) {
                float4 a  = *(const float4*)&xsAll[(kt * BK + k) * BM + ty * 4];
                float4 b0 = *(const float4*)&cs[k * BN + tx * 8];
                float4 b1 = *(const float4*)&cs[k * BN + tx * 8 + 4];
                float av[4] = {a.x, a.y, a.z, a.w};
                float bv[8] = {b0.x, b0.y, b0.z, b0.w, b1.x, b1.y, b1.z, b1.w};
#pragma unroll
                for (int i = 0; i < 4; i++)
#pragma unroll
                    for (int j = 0; j < 8; j++)
                        acc[i][j] = fmaf(av[i], bv[j], acc[i][j]);
            }
        }

        // ---- distances + argmin update (replicate reference rounding) ----
        unsigned long long keymin[4];
#pragma unroll
        for (int i = 0; i < 4; i++) {
            int r = ty * 4 + i;
            float xn = sxnorm[r];
            unsigned long long kk = ~0ull;
#pragma unroll
            for (int j = 0; j < 8; j++) {
                int c = tx * 8 + j;
                float t = __fadd_rn(xn, cnormS[c]);          // fl(xnorm + cnorm)
                float d = __fsub_rn(t, 2.0f * acc[i][j]);    // fl(t - 2*dot)
                unsigned long long key =
                    ((unsigned long long)__float_as_uint(d) << 32) |
                    (unsigned)(c0 + c);
                kk = (key < kk) ? key : kk;                  // tie -> smaller idx
            }
            keymin[i] = kk;
        }
#pragma unroll
        for (int off = 8; off; off >>= 1) {
#pragma unroll
            for (int i = 0; i < 4; i++) {
                unsigned long long o =
                    __shfl_down_sync(0xffffffffu, keymin[i], off, 16);
                keymin[i] = (o < keymin[i]) ? o : keymin[i];
            }
        }
        if (tx == 0) {
#pragma unroll
            for (int i = 0; i < 4; i++) {
                int r = ty * 4 + i;
                unsigned long long cur = sbest[r];
                sbest[r] = (keymin[i] < cur) ? keymin[i] : cur;
            }
        }
    }
    __syncthreads();

    // ---- idx out + epilogue ----
    int* sidx = (int*)cs;   // reuse cs region
    if (tid < BM) {
        int idx = (int)(sbest[tid] & 0xffffffffu);
        sidx[tid] = idx;
        idxout[g * Nrows + n0 + tid] = (float)idx;
    }
    __syncthreads();

    double lsum = 0.0;
#pragma unroll 4
    for (int it = 0; it < (Ee * BM) / NTHREADS; it++) {   // 64
        int elem = it * NTHREADS + tid;
        int e = elem >> 6;
        int m = elem & 63;
        int c = sidx[m];
        float zq = cb[((size_t)(g * NCc + c)) * Ee + e];
        float x  = xsAll[e * BM + m];
        float diff = __fsub_rn(zq, x);          // fl(zq - x)
        float st   = __fadd_rn(x, diff);        // straight-through value
        size_t off = xbase + (size_t)e * Tt + m;
        if (step) {
            qout[off] = __fadd_rn(qout[off], st);     // q1 + q2
        } else {
            qout[off]    = st;
            g_resid[off] = __fsub_rn(x, st);          // residual = x - q1
        }
        lsum += (double)diff * (double)diff;
    }

    // ---- deterministic block loss reduction ----
    __syncthreads();                 // done reading xsAll/sidx
    double* sred = (double*)sm;
    sred[tid] = lsum;
    __syncthreads();
    for (int s2 = NTHREADS / 2; s2 > 0; s2 >>= 1) {
        if (tid < s2) sred[tid] = sred[tid] + sred[tid + s2];
        __syncthreads();
    }
    if (tid == 0) partial[g * ROWTILES + blockIdx.x] = sred[0];
}

// ---------------------------------------------------------------------------
// Final loss: deterministic serial sum of per-block partials.
// ---------------------------------------------------------------------------
__global__ void loss_kernel(float* __restrict__ out) {
    if (threadIdx.x != 0 || blockIdx.x != 0) return;
    double s0 = 0.0, s1 = 0.0;
    for (int i = 0; i < Gg * ROWTILES; i++) s0 += g_partial[i];
    for (int i = 0; i < Gg * ROWTILES; i++) s1 += g_partial[Gg * ROWTILES + i];
    double l0 = 1.25 * (s0 / (double)QELEMS);
    double l1 = 1.25 * (s1 / (double)QELEMS);
    out[0] = (float)((l0 + l1) * 0.5);
}

// ---------------------------------------------------------------------------
extern "C" void kernel_launch(void* const* d_in, const int* in_sizes, int n_in,
                              void* d_out, int out_size) {
    const float* xin = (const float*)d_in[0];
    const float* cb1 = (const float*)d_in[1];
    const float* cb2 = (const float*)d_in[2];
    float* out = (float*)d_out;

    float* qout    = out;                         // [QELEMS]
    float* lossout = out + QELEMS;                // [1]
    float* idxout  = out + QELEMS + 1;            // [2][G][Nrows]

    const int SMEM_BYTES = (Ee * BM + BK * BN + BN + BM) * 4 + BM * 8; // 83200
    cudaFuncSetAttribute(vq_step_kernel,
                         cudaFuncAttributeMaxDynamicSharedMemorySize, SMEM_BYTES);

    cnorm_kernel<<<(2 * Gg * NCc) / 8, 256>>>(cb1, cb2);

    dim3 grid(ROWTILES, Gg);
    vq_step_kernel<<<grid, NTHREADS, SMEM_BYTES>>>(xin, cb1, qout,
                                                   idxout, 0);
    vq_step_kernel<<<grid, NTHREADS, SMEM_BYTES>>>(xin, cb2, qout,
                                                   idxout + Gg * Nrows, 1);
    loss_kernel<<<1, 32>>>(lossout);
}

// round 7
// speedup vs baseline: 1.1503x; 1.1503x over previous
#include <cuda_runtime.h>
#include <cuda_bf16.h>
#include <cstdint>

// ---------------- problem constants ----------------
#define Bb 8
#define Cc 512
#define Tt 4096
#define Gg 2
#define NCc 1024
#define Ee 256
#define Nrows (Bb * Tt)          // 32768 rows per group
#define QELEMS (Bb * Cc * Tt)    // 16777216
#define BM 64                    // rows per CTA
#define BNC 64                   // codes per chunk
#define NCHUNK (NCc / BNC)       // 16
#define NTHREADS 256
#define ROWTILES (Nrows / BM)    // 512
#define KCAND 8

#define SAP 264                  // bf16 elems per staged row (528B, conflict-free ldmatrix)
#define SDP 68                   // float stride of D scratch tile

// ---------------- smem layout (bytes) ----------------
#define SM_A    0                             // 64*SAP bf16 = 33792
#define SM_B    (BM * SAP * 2)                // 33792: B stage / D overlay
#define SM_CN   (SM_B + BM * SAP * 2)         // 67584: 64 f32 cnorm chunk
#define SM_CAND (SM_CN + 256)                 // 67840: 64*8 ints = 2048
#define SM_XN   (SM_CAND + 2048)              // 69888: 64 f32
#define SM_WIN  (SM_XN + 256)                 // 70144: 64 ints
#define SM_RED  (SM_WIN + 256)                // 70400: 256 f64 = 2048
#define SM_TOTAL (SM_RED + 2048)              // 72448
#define XS_STRIDE 257                         // fp32 rescore overlay at SM_A (65792 B)

// ---------------- scratch ----------------
__device__ float  g_resid[QELEMS];
__device__ float  g_cnorm[2 * Gg * NCc];
__device__ double g_partial[2 * Gg * ROWTILES];   // 4096

// ---------------- helpers ----------------
__device__ __forceinline__ uint32_t smem_u32(const void* p) {
    uint32_t a;
    asm("{ .reg .u64 t; cvta.to.shared.u64 t, %1; cvt.u32.u64 %0, t; }"
        : "=r"(a) : "l"(p));
    return a;
}

__device__ __forceinline__ void ldsm_x4(uint32_t* r, uint32_t addr) {
    asm volatile("ldmatrix.sync.aligned.m8n8.x4.shared.b16 {%0,%1,%2,%3}, [%4];"
                 : "=r"(r[0]), "=r"(r[1]), "=r"(r[2]), "=r"(r[3]) : "r"(addr));
}

__device__ __forceinline__ void mma16816(float* c, const uint32_t* a,
                                         uint32_t b0, uint32_t b1) {
    asm volatile(
        "mma.sync.aligned.m16n8k16.row.col.f32.bf16.bf16.f32 "
        "{%0,%1,%2,%3}, {%4,%5,%6,%7}, {%8,%9}, {%0,%1,%2,%3};"
        : "+f"(c[0]), "+f"(c[1]), "+f"(c[2]), "+f"(c[3])
        : "r"(a[0]), "r"(a[1]), "r"(a[2]), "r"(a[3]), "r"(b0), "r"(b1));
}

// ---------------------------------------------------------------------------
__global__ void cnorm_kernel(const float* __restrict__ cb1,
                             const float* __restrict__ cb2) {
    int gwarp = (blockIdx.x * blockDim.x + threadIdx.x) >> 5;
    int lane  = threadIdx.x & 31;
    if (gwarp >= 2 * Gg * NCc) return;
    const float* cb = (gwarp < Gg * NCc) ? cb1 : cb2;
    int row = gwarp & (Gg * NCc - 1);
    const float* p = cb + (size_t)row * Ee;
    float s = 0.f;
#pragma unroll
    for (int i = 0; i < Ee / 32; i++) {
        float v = p[lane + i * 32];
        s = __fadd_rn(s, __fmul_rn(v, v));
    }
#pragma unroll
    for (int off = 16; off; off >>= 1) s += __shfl_xor_sync(0xffffffffu, s, off);
    if (lane == 0) g_cnorm[gwarp] = s;
}

// ---------------------------------------------------------------------------
__global__ __launch_bounds__(NTHREADS, 2)
void vq_step_mma(const float* __restrict__ xin,
                 const float* __restrict__ cb,
                 float* __restrict__ qout,
                 float* __restrict__ idxout,
                 int step) {
    extern __shared__ char sm[];
    uint32_t smb = smem_u32(sm);
    float* cnormS = (float*)(sm + SM_CN);
    int*   cands  = (int*)(sm + SM_CAND);
    float* sxn    = (float*)(sm + SM_XN);
    int*   win    = (int*)(sm + SM_WIN);
    double* sred  = (double*)(sm + SM_RED);
    float* xs     = (float*)(sm + SM_A);          // rescore overlay

    const float* src = step ? g_resid : xin;
    const float* cnorm = g_cnorm + step * (Gg * NCc);
    double* partial = g_partial + step * (Gg * ROWTILES);

    int tid  = threadIdx.x;
    int lane = tid & 31;
    int wid  = tid >> 5;
    int wm   = wid & 3;         // m quarter (16 rows)
    int wn   = wid >> 2;        // n half (32 codes)
    int g    = blockIdx.y;
    int n0   = blockIdx.x * BM;
    int b    = n0 >> 12;
    int t0   = n0 & (Tt - 1);
    size_t xbase = ((size_t)b * Cc + (size_t)g * Ee) * Tt + t0;
    const float* cbg = cb + (size_t)g * NCc * Ee;

    // ---- stage A: x[64 t-rows x 256 e] fp32 -> bf16, row stride SAP ----
#pragma unroll
    for (int i = 0; i < 8; i++) {                  // 2048 (e-pair, t4) tasks
        int f  = tid + i * NTHREADS;
        int e  = (f >> 4) << 1;                    // even e (0..254)
        int t4 = (f & 15) << 2;                    // 0..60
        float4 v0 = *(const float4*)(src + xbase + (size_t)e * Tt + t4);
        float4 v1 = *(const float4*)(src + xbase + (size_t)(e + 1) * Tt + t4);
        __nv_bfloat162 h0 = __floats2bfloat162_rn(v0.x, v1.x);
        __nv_bfloat162 h1 = __floats2bfloat162_rn(v0.y, v1.y);
        __nv_bfloat162 h2 = __floats2bfloat162_rn(v0.z, v1.z);
        __nv_bfloat162 h3 = __floats2bfloat162_rn(v0.w, v1.w);
        *(uint32_t*)(sm + SM_A + (size_t)((t4 + 0) * SAP + e) * 2) = *(uint32_t*)&h0;
        *(uint32_t*)(sm + SM_A + (size_t)((t4 + 1) * SAP + e) * 2) = *(uint32_t*)&h1;
        *(uint32_t*)(sm + SM_A + (size_t)((t4 + 2) * SAP + e) * 2) = *(uint32_t*)&h2;
        *(uint32_t*)(sm + SM_A + (size_t)((t4 + 3) * SAP + e) * 2) = *(uint32_t*)&h3;
    }

    // ldmatrix base addresses (bytes)
    uint32_t aAddr = smb + SM_A +
        (uint32_t)(((wm * 16 + (lane & 15)) * SAP + ((lane >> 4) << 3)) * 2);
    uint32_t bAddr = smb + SM_B +
        (uint32_t)(((wn * 32 + (lane & 7) + ((lane >> 4) << 3)) * SAP +
                    (((lane >> 3) & 1) << 3)) * 2);

    // per-row top-K candidates (row = tid for tid < 64)
    float cd[KCAND];
    int   ci[KCAND];
#pragma unroll
    for (int s = 0; s < KCAND; s++) { cd[s] = __int_as_float(0x7f800000); ci[s] = 0; }
    float worst = __int_as_float(0x7f800000);

    for (int ct = 0; ct < NCHUNK; ct++) {
        int c0 = ct * BNC;
        // ---- stage B chunk: codes [c0, c0+64) x 256 e -> bf16 stride SAP ----
#pragma unroll
        for (int i = 0; i < 16; i++) {             // 4096 (code,k4) tasks
            int f4 = tid + i * NTHREADS;
            int code = f4 >> 6;                    // 0..63
            int k4 = (f4 & 63) << 2;
            float4 v = *(const float4*)(cbg + (size_t)(c0 + code) * Ee + k4);
            __nv_bfloat162 h0 = __floats2bfloat162_rn(v.x, v.y);
            __nv_bfloat162 h1 = __floats2bfloat162_rn(v.z, v.w);
            *(uint2*)(sm + SM_B + (size_t)(code * SAP + k4) * 2) =
                make_uint2(*(uint32_t*)&h0, *(uint32_t*)&h1);
        }
        if (tid < BNC) cnormS[tid] = cnorm[g * NCc + c0 + tid];
        __syncthreads();

        // ---- GEMM: warp 16x32 tile, K=256 via 16 k-steps ----
        float acc[4][4];
#pragma unroll
        for (int j = 0; j < 4; j++)
#pragma unroll
            for (int r = 0; r < 4; r++) acc[j][r] = 0.f;

#pragma unroll 4
        for (int ks = 0; ks < 16; ks++) {
            uint32_t afr[4];
            ldsm_x4(afr, aAddr + (uint32_t)((ks * 16) * 2));
            uint32_t bfr[2][4];
#pragma unroll
            for (int jp = 0; jp < 2; jp++)
                ldsm_x4(bfr[jp], bAddr + (uint32_t)((jp * 16 * SAP + ks * 16) * 2));
#pragma unroll
            for (int j = 0; j < 4; j++)
                mma16816(acc[j], afr,
                         bfr[j >> 1][(j & 1) * 2], bfr[j >> 1][(j & 1) * 2 + 1]);
        }
        __syncthreads();   // all warps done reading sB before D overlay

        // ---- dump D tile (dot products) into sB region, stride SDP ----
#pragma unroll
        for (int j = 0; j < 4; j++) {
            int m = wm * 16 + (lane >> 2);
            int n = wn * 32 + j * 8 + ((lane & 3) << 1);
            *(float2*)(sm + SM_B + (size_t)(m * SDP + n) * 4) =
                make_float2(acc[j][0], acc[j][1]);
            *(float2*)(sm + SM_B + (size_t)((m + 8) * SDP + n) * 4) =
                make_float2(acc[j][2], acc[j][3]);
        }
        __syncthreads();

        // ---- scan: thread=row, 64 cols ----
        if (tid < BM) {
            const float* sD = (const float*)(sm + SM_B) + tid * SDP;
#pragma unroll 8
            for (int cl = 0; cl < BNC; cl++) {
                float v = cnormS[cl] - 2.0f * sD[cl];
                if (v < worst) {
                    float mx = cd[0]; int ms = 0;
#pragma unroll
                    for (int s = 1; s < KCAND; s++)
                        if (cd[s] > mx) { mx = cd[s]; ms = s; }
#pragma unroll
                    for (int s = 0; s < KCAND; s++)
                        if (s == ms) { cd[s] = v; ci[s] = c0 + cl; }
                    float w = cd[0];
#pragma unroll
                    for (int s = 1; s < KCAND; s++) w = fmaxf(w, cd[s]);
                    worst = w;
                }
            }
        }
        __syncthreads();   // sD dead before next chunk's B staging
    }

    // dump candidates
    if (tid < BM) {
#pragma unroll
        for (int s = 0; s < KCAND; s++) cands[tid * KCAND + s] = ci[s];
    }
    __syncthreads();

    // ---- overlay: stage x fp32 tile [row][e] stride XS_STRIDE ----
#pragma unroll
    for (int i = 0; i < 16; i++) {                 // 4096 float4 tasks
        int f4 = tid + i * NTHREADS;
        int e  = f4 >> 4;
        int t4 = (f4 & 15) << 2;
        float4 v = *(const float4*)(src + xbase + (size_t)e * Tt + t4);
        xs[(t4 + 0) * XS_STRIDE + e] = v.x;
        xs[(t4 + 1) * XS_STRIDE + e] = v.y;
        xs[(t4 + 2) * XS_STRIDE + e] = v.z;
        xs[(t4 + 3) * XS_STRIDE + e] = v.w;
    }
    __syncthreads();

    // ---- xnorm: canonical sequential order (matches round-1 exactly) ----
    if (tid < BM) {
        float s = 0.f;
        const float* xr = xs + tid * XS_STRIDE;
        for (int e = 0; e < Ee; e++) s = __fadd_rn(s, __fmul_rn(xr[e], xr[e]));
        sxn[tid] = s;
    }
    __syncthreads();

    // ---- exact fp32 rescore: 4 threads per row, 2 cands each ----
    {
        int row = tid >> 2;
        int cbase = (tid & 3) * 2;
        const float* xr = xs + row * XS_STRIDE;
        float xn = sxn[row];
        unsigned long long best = ~0ull;
#pragma unroll
        for (int cj = 0; cj < 2; cj++) {
            int c = cands[row * KCAND + cbase + cj];
            const float* cw = cbg + (size_t)c * Ee;
            float acc = 0.f;
            for (int k = 0; k < Ee; k++) acc = fmaf(xr[k], __ldg(cw + k), acc);
            float d = __fsub_rn(__fadd_rn(xn, cnorm[g * NCc + c]), 2.0f * acc);
            unsigned long long key =
                ((unsigned long long)__float_as_uint(d) << 32) | (unsigned)c;
            best = (key < best) ? key : best;
        }
        unsigned long long o = __shfl_xor_sync(0xffffffffu, best, 1);
        best = (o < best) ? o : best;
        o = __shfl_xor_sync(0xffffffffu, best, 2);
        best = (o < best) ? o : best;
        if ((tid & 3) == 0) win[row] = (int)(best & 0xffffffffu);
    }
    __syncthreads();

    if (tid < BM) idxout[g * Nrows + n0 + tid] = (float)win[tid];

    // ---- epilogue: q / resid / loss ----
    double lsum = 0.0;
#pragma unroll 4
    for (int it = 0; it < (Ee * BM) / NTHREADS; it++) {    // 64
        int elem = it * NTHREADS + tid;
        int e = elem >> 6;
        int m = elem & 63;
        int c = win[m];
        float zq = __ldg(cbg + (size_t)c * Ee + e);
        float x  = xs[m * XS_STRIDE + e];
        float diff = __fsub_rn(zq, x);
        float st   = __fadd_rn(x, diff);
        size_t off = xbase + (size_t)e * Tt + m;
        if (step) {
            qout[off] = __fadd_rn(qout[off], st);
        } else {
            qout[off]    = st;
            g_resid[off] = __fsub_rn(x, st);
        }
        lsum += (double)diff * (double)diff;
    }

    __syncthreads();
    sred[tid] = lsum;
    __syncthreads();
    for (int s2 = NTHREADS / 2; s2 > 0; s2 >>= 1) {
        if (tid < s2) sred[tid] = sred[tid] + sred[tid + s2];
        __syncthreads();
    }
    if (tid == 0) partial[g * ROWTILES + blockIdx.x] = sred[0];
}

// ---------------------------------------------------------------------------
__global__ void loss_kernel(float* __restrict__ out) {
    __shared__ double s0a[256], s1a[256];
    int tid = threadIdx.x;
    double a0 = 0.0, a1 = 0.0;
#pragma unroll
    for (int i = 0; i < 4; i++) {
        a0 += g_partial[tid * 4 + i];
        a1 += g_partial[Gg * ROWTILES + tid * 4 + i];
    }
    s0a[tid] = a0; s1a[tid] = a1;
    __syncthreads();
    for (int s = 128; s > 0; s >>= 1) {
        if (tid < s) { s0a[tid] += s0a[tid + s]; s1a[tid] += s1a[tid + s]; }
        __syncthreads();
    }
    if (tid == 0) {
        double l0 = 1.25 * (s0a[0] / (double)QELEMS);
        double l1 = 1.25 * (s1a[0] / (double)QELEMS);
        out[0] = (float)((l0 + l1) * 0.5);
    }
}

// ---------------------------------------------------------------------------
extern "C" void kernel_launch(void* const* d_in, const int* in_sizes, int n_in,
                              void* d_out, int out_size) {
    const float* xin = (const float*)d_in[0];
    const float* cb1 = (const float*)d_in[1];
    const float* cb2 = (const float*)d_in[2];
    float* out = (float*)d_out;

    float* qout    = out;
    float* lossout = out + QELEMS;
    float* idxout  = out + QELEMS + 1;

    cudaFuncSetAttribute(vq_step_mma,
                         cudaFuncAttributeMaxDynamicSharedMemorySize, SM_TOTAL);

    cnorm_kernel<<<(2 * Gg * NCc) / 8, 256>>>(cb1, cb2);

    dim3 grid(ROWTILES, Gg);
    vq_step_mma<<<grid, NTHREADS, SM_TOTAL>>>(xin, cb1, qout, idxout, 0);
    vq_step_mma<<<grid, NTHREADS, SM_TOTAL>>>(xin, cb2, qout,
                                              idxout + Gg * Nrows, 1);
    loss_kernel<<<1, 256>>>(lossout);
}